// round 12
// baseline (speedup 1.0000x reference)
#include <cuda_runtime.h>

#define IMG_H 1024
#define IMG_W 1024
#define NBATCH 16
#define NPIX (NBATCH * IMG_H * IMG_W)
#define OVF_CAP (1u << 23)
#define FULLM 0xffffffffu
#define M34 ((1ull << 34) - 1ull)

// k_front tiling: 64x64 output, +/-4 halo
#define TS 64
#define TIN 72      // input tile  (TS+8)
#define THB 68      // h-blurred / S / mag stride (TS+4)

// ---------------- scratch (static device globals; no allocation) ----------------
__device__ float    g_tu[NPIX];          // SQUARED NMS-surviving magnitude
__device__ unsigned g_bmax[NBATCH];      // per-batch max mag^2 (float bits)
__device__ unsigned g_tumax[NBATCH];     // per-batch max thin^2 (float bits)
__device__ float    g_lo2[NBATCH];
__device__ float    g_hi2[NBATCH];
__device__ unsigned g_ovfn[2];
__device__ unsigned g_ovfq[2][OVF_CAP];
__device__ unsigned g_bar_cnt;
__device__ unsigned g_bar_gen;

__constant__ int c_dy[8] = {0, 1, 1, 1, 0, -1, -1, -1};
__constant__ int c_dx[8] = {1, 1, 0, -1, -1, -1, 0, 1};

#define GW0 0.13533528323661270f
#define GW1 0.60653065971263342f
#define T1C 0.41421356237309503f
#define T2C 2.41421356237309510f
#define LOW_T_C 0.00392f
#define HIGH_T_C 0.15f
#define STRONG_BITS 0x437F0000u

// ---------------- K0 ----------------
__global__ void k_init() {
    int t = threadIdx.x;
    if (t < NBATCH) { g_bmax[t] = 0u; g_tumax[t] = 0u; }
    if (t < 2) g_ovfn[t] = 0u;
    if (t == 0) { g_bar_cnt = 0u; g_bar_gen = 0u; }
}

__device__ __forceinline__ int sector_of(float Ix, float Iy) {
    float axv = fabsf(Ix), ayv = fabsf(Iy);
    if (ayv <= T1C * axv)       return (Ix >= 0.f) ? 4 : 0;
    else if (ayv >= T2C * axv)  return (Iy > 0.f) ? 6 : 2;
    else                        return (Iy > 0.f) ? ((Ix > 0.f) ? 5 : 7)
                                                  : ((Ix > 0.f) ? 3 : 1);
}

// ---------------- K1: fused blur + sobel + mag^2 + sector + NMS -------------------
// 2D work decomposition: tx = tid & 63 owns column tx (and tx+64 when predicated),
// rows walk r = ty, r += 16. No integer div/mod anywhere in the hot loops.

__device__ __forceinline__ void front_tail(float* sB, unsigned char* sK,
                                           float* red1, float* red2) {
    const int bb  = blockIdx.z;
    const int gy0 = blockIdx.y * TS, gx0 = blockIdx.x * TS;
    const int tid = threadIdx.x;
    const int tx = tid & 63, tyq = tid >> 6;
    float bm = 0.f, tm = 0.f;
#pragma unroll
    for (int j = 0; j < 4; j++) {
        int oy = tyq + j * 16, ox = tx;
        float mc = sB[(oy + 1) * THB + (ox + 1)];
        int k = sK[oy * TS + ox];
        int dy = c_dy[k], dx = c_dx[k];
        float mp = sB[(oy + 1 + dy) * THB + (ox + 1 + dx)];
        float mn = sB[(oy + 1 - dy) * THB + (ox + 1 - dx)];
        float tu = (mc > mp && mc > mn) ? mc : 0.f;
        unsigned p = ((unsigned)bb << 20) | ((unsigned)(gy0 + oy) << 10) | (unsigned)(gx0 + ox);
        g_tu[p] = tu;
        bm = fmaxf(bm, mc); tm = fmaxf(tm, tu);
    }
    for (int o = 16; o; o >>= 1) {
        bm = fmaxf(bm, __shfl_xor_sync(FULLM, bm, o));
        tm = fmaxf(tm, __shfl_xor_sync(FULLM, tm, o));
    }
    if ((tid & 31) == 0) { red1[tid >> 5] = bm; red2[tid >> 5] = tm; }
    __syncthreads();
    if (tid < 32) {
        bm = red1[tid]; tm = red2[tid];
        for (int o = 16; o; o >>= 1) {
            bm = fmaxf(bm, __shfl_xor_sync(FULLM, bm, o));
            tm = fmaxf(tm, __shfl_xor_sync(FULLM, tm, o));
        }
        if (tid == 0) {
            atomicMax(&g_bmax[bb],  __float_as_uint(bm));
            atomicMax(&g_tumax[bb], __float_as_uint(tm));
        }
    }
}

__device__ __forceinline__ void vblur_col(float* sA, const float* sB, int r, int c,
                                          bool border, int gy0, int gx0) {
    const float* p = sB + r * THB + c;
    float v = GW0 * p[0] + GW1 * p[THB] + p[2 * THB] + GW1 * p[3 * THB] + GW0 * p[4 * THB];
    if (border) {
        int gy = gy0 - 2 + r, gx = gx0 - 2 + c;
        if ((unsigned)gy >= IMG_H || (unsigned)gx >= IMG_W) v = 0.f;
    }
    sA[r * THB + c] = v;
}

__device__ __forceinline__ void mag_col(float* sB, const float* sA, unsigned char* sK,
                                        int r, int c, bool border, int gy0, int gx0) {
    const float* s = sA + r * THB + c;
    float s00 = s[0],       s01 = s[1],           s02 = s[2];
    float s10 = s[THB],                           s12 = s[THB + 2];
    float s20 = s[2 * THB], s21 = s[2 * THB + 1], s22 = s[2 * THB + 2];
    float Ix = (s00 - s02) + 2.f * (s10 - s12) + (s20 - s22);
    float Iy = (s00 + 2.f * s01 + s02) - (s20 + 2.f * s21 + s22);
    float m = Ix * Ix + Iy * Iy;
    if (border) {
        int gy = gy0 - 1 + r, gx = gx0 - 1 + c;
        if ((unsigned)gy >= IMG_H || (unsigned)gx >= IMG_W) { m = 0.f; Ix = 0.f; Iy = 0.f; }
    }
    sB[r * THB + c] = m;
    if ((unsigned)(r - 1) < TS && (unsigned)(c - 1) < TS)
        sK[(r - 1) * TS + (c - 1)] = (unsigned char)sector_of(Ix, Iy);
}

template <bool BORDER>
__device__ __forceinline__ void front_body(const float* __restrict__ img,
                                           float* sA, float* sB, unsigned char* sK,
                                           float* red1, float* red2) {
    const int bb  = blockIdx.z;
    const int gy0 = blockIdx.y * TS, gx0 = blockIdx.x * TS;
    const int tid = threadIdx.x;
    const int tx = tid & 63, ty = tid >> 6;
    const float* im = img + bb * (IMG_H * IMG_W);

    // ---- load 72x72 (origin gy0-4, gx0-4): col tx, plus tx+64 for tx<8 ----
    if (BORDER) {
        for (int r = ty; r < TIN; r += 16) {
            int gy = gy0 - 4 + r;
            int gx = gx0 - 4 + tx;
            float v = 0.f;
            if ((unsigned)gy < IMG_H && (unsigned)gx < IMG_W) v = __ldg(&im[gy * IMG_W + gx]);
            sA[r * TIN + tx] = v;
            if (tx < 8) {
                int gx2 = gx + 64;
                float v2 = 0.f;
                if ((unsigned)gy < IMG_H && (unsigned)gx2 < IMG_W) v2 = __ldg(&im[gy * IMG_W + gx2]);
                sA[r * TIN + tx + 64] = v2;
            }
        }
    } else {
        const float* org = im + (gy0 - 4) * IMG_W + (gx0 - 4);
        for (int r = ty; r < TIN; r += 16) {
            const float* row = org + r * IMG_W;
            sA[r * TIN + tx] = __ldg(row + tx);
            if (tx < 8) sA[r * TIN + tx + 64] = __ldg(row + tx + 64);
        }
    }
    __syncthreads();

    // ---- horizontal blur: 72 rows x 68 cols -> sB ----
    for (int r = ty; r < TIN; r += 16) {
        const float* row = sA + r * TIN;
        float* orow = sB + r * THB;
        orow[tx] = GW0 * row[tx] + GW1 * row[tx + 1] + row[tx + 2]
                 + GW1 * row[tx + 3] + GW0 * row[tx + 4];
        if (tx < 4) {
            int c = tx + 64;
            orow[c] = GW0 * row[c] + GW1 * row[c + 1] + row[c + 2]
                    + GW1 * row[c + 3] + GW0 * row[c + 4];
        }
    }
    __syncthreads();

    // ---- vertical blur: 68 rows x 68 cols -> sA (stride THB) ----
    for (int r = ty; r < THB; r += 16) {
        vblur_col(sA, sB, r, tx, BORDER, gy0, gx0);
        if (tx < 4) vblur_col(sA, sB, r, tx + 64, BORDER, gy0, gx0);
    }
    __syncthreads();

    // ---- mag^2 + sector: 66 rows x 66 cols -> sB (stride THB) ----
    for (int r = ty; r < 66; r += 16) {
        mag_col(sB, sA, sK, r, tx, BORDER, gy0, gx0);
        if (tx < 2) mag_col(sB, sA, sK, r, tx + 64, BORDER, gy0, gx0);
    }
    __syncthreads();

    front_tail(sB, sK, red1, red2);
}

__global__ __launch_bounds__(1024) void k_front(const float* __restrict__ img) {
    __shared__ float sA[TIN * TIN];
    __shared__ float sB[TIN * THB];
    __shared__ unsigned char sK[TS * TS];
    __shared__ float red1[32], red2[32];
    bool border = (blockIdx.x == 0) | (blockIdx.x == gridDim.x - 1) |
                  (blockIdx.y == 0) | (blockIdx.y == gridDim.y - 1);
    if (border) front_body<true>(img, sA, sB, sK, red1, red2);
    else        front_body<false>(img, sA, sB, sK, red1, red2);
}

// ---------------- K1.5: per-batch squared thresholds ------------------------------
__global__ void k_thresh() {
    __shared__ float s_hi;
    int t = threadIdx.x;
    if (t == 0) {
        float tmax = 0.f;
#pragma unroll
        for (int i = 0; i < NBATCH; i++) {
            float bm2 = __uint_as_float(g_bmax[i]);
            float tm2 = __uint_as_float(g_tumax[i]);
            if (bm2 > 0.f) tmax = fmaxf(tmax, sqrtf(tm2) / sqrtf(bm2));
        }
        s_hi = tmax * HIGH_T_C;
    }
    __syncthreads();
    if (t < NBATCH) {
        float bm = sqrtf(__uint_as_float(g_bmax[t]));
        float lo = LOW_T_C * bm, hi = s_hi * bm;
        g_lo2[t] = lo * lo;
        g_hi2[t] = hi * hi;
    }
}

// ---------------- bounded DFS expansion (claim via CAS) ---------------------------
__device__ __forceinline__ void expand_from(unsigned seed, float* out,
                                            float lo2, float hi2,
                                            int qidx, int maxpops) {
    unsigned stk[96];
    int sp = 0, pops = 0;
    unsigned cur = seed;
    const unsigned base = cur & ~0xFFFFFu;
    while (true) {
        int y = (cur >> 10) & 1023;
        int x = cur & 1023;
#pragma unroll
        for (int d = 0; d < 8; d++) {
            int ny = y + c_dy[d], nx = x + c_dx[d];
            if ((unsigned)ny < IMG_H && (unsigned)nx < IMG_W) {
                unsigned n = base | ((unsigned)ny << 10) | (unsigned)nx;
                float t = __ldg(&g_tu[n]);
                if (t < hi2 && t >= lo2) {
                    unsigned old = atomicCAS((unsigned*)&out[n], 0u, STRONG_BITS);
                    if (old == 0u) {
                        if (sp < 96) stk[sp++] = n;
                        else {
                            unsigned pos = atomicAdd(&g_ovfn[qidx], 1u);
                            if (pos < OVF_CAP) g_ovfq[qidx][pos] = n;
                        }
                    }
                }
            }
        }
        if (sp == 0) break;
        if (++pops > maxpops) {
            while (sp > 0) {
                unsigned v = stk[--sp];
                unsigned pos = atomicAdd(&g_ovfn[qidx], 1u);
                if (pos < OVF_CAP) g_ovfq[qidx][pos] = v;
            }
            break;
        }
        cur = stk[--sp];
    }
}

// ---------------- K2: warp-bitboard tile hysteresis + inline cross-tile expansion --
__global__ __launch_bounds__(256) void k_seed(float* __restrict__ out) {
    const int lane = threadIdx.x & 31;
    const int tileId = blockIdx.x * 8 + (threadIdx.x >> 5);   // 16384 32x32 tiles
    const int bb = tileId >> 10;
    const int t  = tileId & 1023;
    const int gy0 = (t >> 5) << 5, gx0 = (t & 31) << 5;
    const float* tu = g_tu + (bb << 20);
    const float hi2 = g_hi2[bb], lo2 = g_lo2[bb];

    unsigned long long sm = 0, wm = 0;
    unsigned long long ht_s = 0, ht_w = 0;
    unsigned long long hb_s = 0, hb_w = 0;

    for (int r = 0; r < 34; r++) {
        int gy = gy0 - 1 + r;
        float v = 0.f, v2 = 0.f;
        if ((unsigned)gy < IMG_H) {
            int gx = gx0 - 1 + lane;
            if ((unsigned)gx < IMG_W) v = __ldg(&tu[(gy << 10) + gx]);
            int gx2 = gx0 + 31 + lane;
            if (lane < 2 && (unsigned)gx2 < IMG_W) v2 = __ldg(&tu[(gy << 10) + gx2]);
        }
        unsigned bs  = __ballot_sync(FULLM, v >= hi2);
        unsigned bw  = __ballot_sync(FULLM, v >= lo2 && v < hi2);
        unsigned bs2 = __ballot_sync(FULLM, lane < 2 && v2 >= hi2);
        unsigned bw2 = __ballot_sync(FULLM, lane < 2 && v2 >= lo2 && v2 < hi2);
        unsigned long long rs = (unsigned long long)bs | ((unsigned long long)(bs2 & 3u) << 32);
        unsigned long long rw = (unsigned long long)bw | ((unsigned long long)(bw2 & 3u) << 32);
        if (r == 0)        { ht_s = rs; ht_w = rw; }
        else if (r == 33)  { hb_s = rs; hb_w = rw; }
        else if (lane == r - 1) { sm = rs; wm = rw; }
    }

    // fixpoint: s |= w & dilate8(s)
    unsigned long long s = sm, hts = ht_s, hbs = hb_s;
    while (true) {
        unsigned long long up = __shfl_up_sync(FULLM, s, 1);
        if (lane == 0)  up = hts;
        unsigned long long dn = __shfl_down_sync(FULLM, s, 1);
        if (lane == 31) dn = hbs;
        unsigned long long dil = (s << 1) | (s >> 1)
                               | up | (up << 1) | (up >> 1)
                               | dn | (dn << 1) | (dn >> 1);
        unsigned long long ns = s | (wm & dil & M34);
        unsigned long long row0  = __shfl_sync(FULLM, s, 0);
        unsigned long long row31 = __shfl_sync(FULLM, s, 31);
        unsigned long long nht = hts | (ht_w & ((hts << 1) | (hts >> 1) | row0  | (row0 << 1)  | (row0 >> 1))  & M34);
        unsigned long long nhb = hbs | (hb_w & ((hbs << 1) | (hbs >> 1) | row31 | (row31 << 1) | (row31 >> 1)) & M34);
        bool ch = (ns != s) || (nht != hts) || (nhb != hbs);
        s = ns; hts = nht; hbs = nhb;
        if (!__any_sync(FULLM, ch)) break;
    }

    // sparse coalesced 255 writes (out pre-zeroed by memset)
    const unsigned obase = ((unsigned)bb << 20) + ((unsigned)gy0 << 10) + (unsigned)gx0;
#pragma unroll 4
    for (int r = 0; r < 32; r++) {
        unsigned long long m = __shfl_sync(FULLM, s, r);
        if ((m >> (lane + 1)) & 1ull)
            out[obase + ((unsigned)r << 10) + lane] = 255.0f;
    }

    // inline expansion from promoted interior pixels with out-of-tile weak neighbor
    unsigned long long prom = s & ~sm;
    unsigned long long wup = __shfl_up_sync(FULLM, wm, 1);
    if (lane == 0)  wup = ht_w;
    unsigned long long wdn = __shfl_down_sync(FULLM, wm, 1);
    if (lane == 31) wdn = hb_w;
    unsigned long long wvert = wup | wm | wdn;
    unsigned long long oow = 0;
    if (wvert & 1ull)            oow |= 2ull;
    if ((wvert >> 33) & 1ull)    oow |= (1ull << 32);
    if (lane == 0)  oow |= (ht_w | (ht_w << 1) | (ht_w >> 1));
    if (lane == 31) oow |= (hb_w | (hb_w << 1) | (hb_w >> 1));
    unsigned long long push = prom & oow & 0x1FFFFFFFEull;
    while (push) {
        int c = __ffsll((long long)push) - 1;
        push &= push - 1;
        unsigned p = ((unsigned)bb << 20) | ((unsigned)(gy0 + lane) << 10) | (unsigned)(gx0 + c - 1);
        expand_from(p, out, lo2, hi2, 0, 96);
    }
}

// ---------------- K3: persistent drain (backstop for spills) ----------------------
__device__ __forceinline__ void gsync() {
    __syncthreads();
    if (threadIdx.x == 0) {
        unsigned gen = atomicAdd(&g_bar_gen, 0u);
        __threadfence();
        if (atomicAdd(&g_bar_cnt, 1u) == gridDim.x - 1) {
            atomicExch(&g_bar_cnt, 0u);
            __threadfence();
            atomicAdd(&g_bar_gen, 1u);
        } else {
            while (atomicAdd(&g_bar_gen, 0u) == gen) __nanosleep(100);
        }
        __threadfence();
    }
    __syncthreads();
}

__global__ __launch_bounds__(256, 2) void k_drain(float* __restrict__ out) {
    int curq = 0;
    while (true) {
        unsigned n = atomicAdd(&g_ovfn[curq], 0u);
        if (n == 0u) break;
        if (n > OVF_CAP) n = OVF_CAP;
        const unsigned stride = gridDim.x * blockDim.x;
        for (unsigned i = blockIdx.x * blockDim.x + threadIdx.x; i < n; i += stride) {
            unsigned p = __ldcg(&g_ovfq[curq][i]);
            int bb = p >> 20;
            expand_from(p, out, g_lo2[bb], g_hi2[bb], curq ^ 1, 64);
        }
        gsync();
        if (blockIdx.x == 0 && threadIdx.x == 0) atomicExch(&g_ovfn[curq], 0u);
        gsync();
        curq ^= 1;
    }
}

// ---------------- launch ----------------
extern "C" void kernel_launch(void* const* d_in, const int* in_sizes, int n_in,
                              void* d_out, int out_size) {
    const float* img = (const float*)d_in[0];
    float* out = (float*)d_out;
    (void)in_sizes; (void)n_in; (void)out_size;

    k_init<<<1, 32>>>();
    cudaMemsetAsync(out, 0, (size_t)NPIX * sizeof(float));
    dim3 b1(1024), g1(IMG_W / TS, IMG_H / TS, NBATCH);
    k_front<<<g1, b1>>>(img);
    k_thresh<<<1, 32>>>();
    k_seed<<<2048, 256>>>(out);
    k_drain<<<296, 256>>>(out);
}